// round 6
// baseline (speedup 1.0000x reference)
#include <cuda_runtime.h>
#include <cstdint>

// Problem constants (match reference setup_inputs)
#define NN 100000
#define EE 1600000
#define DD 64

// Scratch aggregation buffer. float4 for guaranteed 16B alignment.
__device__ float4 g_agg4[(size_t)NN * (DD / 4)];

// 1 if edge_index buffer is int64, 0 if int32 (JAX x64-disabled downgrades).
__device__ int g_idx_is64;

// ---------------------------------------------------------------------------
// Phase 0: detect index width. Indices < 2^17, so int64 => odd words all 0.
// ---------------------------------------------------------------------------
__global__ void detect_kernel(const unsigned int* __restrict__ ei_words) {
    int zeros = 0;
    #pragma unroll
    for (int i = 0; i < 64; i++) zeros += (ei_words[2 * i + 1] == 0u) ? 1 : 0;
    g_idx_is64 = (zeros >= 60) ? 1 : 0;
}

// ---------------------------------------------------------------------------
// Phase B: zero the aggregation buffer
// ---------------------------------------------------------------------------
__global__ void __launch_bounds__(256) zero_agg_kernel() {
    int i = blockIdx.x * blockDim.x + threadIdx.x;
    const int total4 = NN * (DD / 4);
    if (i < total4) g_agg4[i] = make_float4(0.f, 0.f, 0.f, 0.f);
}

// ---------------------------------------------------------------------------
// Phase A: edge scatter. 16 threads/edge, red.global.add.v4 into g_agg.
// ---------------------------------------------------------------------------
__global__ void __launch_bounds__(256) scatter_kernel(
    const float* __restrict__ x,
    const void* __restrict__ edge_index, // [2, E], int32 or int64
    const float* __restrict__ edge_attr)
{
    int gid = blockIdx.x * blockDim.x + threadIdx.x;
    int e = gid >> 4;
    int q = gid & 15;
    if (e >= EE) return;

    int src, dst;
    if (g_idx_is64) {
        const long long* ei = (const long long*)edge_index;
        src = (int)ei[e];
        dst = (int)ei[EE + e];
    } else {
        const int* ei = (const int*)edge_index;
        src = ei[e];
        dst = ei[EE + e];
    }
    float w = edge_attr[e];

    float4 v = reinterpret_cast<const float4*>(x)[(size_t)src * 16 + q];
    v.x *= w; v.y *= w; v.z *= w; v.w *= w;

    float* p = (float*)(g_agg4 + (size_t)dst * 16 + q);
    asm volatile("red.global.add.v4.f32 [%0], {%1, %2, %3, %4};"
                 :: "l"(p), "f"(v.x), "f"(v.y), "f"(v.z), "f"(v.w)
                 : "memory");
}

// ---------------------------------------------------------------------------
// Phase C: out = relu(agg @ W_rel^T + b_rel + x @ W_root^T)
// 256 threads/block, 64 nodes/block, 4x4 register tile per thread.
// k-loop chunked by 4: all shared loads are LDS.128 (16 per 128 FFMA).
// Weights transposed in shared as [k][o]; rows padded to 68 floats (16B mult).
// ---------------------------------------------------------------------------
#define ROWPAD 68

// acc += a * wr + xv * wo (componentwise, 8 FFMA)
#define FMA4(acc, a, wr, xv, wo)                \
    do {                                        \
        (acc).x += (a) * (wr).x + (xv) * (wo).x; \
        (acc).y += (a) * (wr).y + (xv) * (wo).y; \
        (acc).z += (a) * (wr).z + (xv) * (wo).z; \
        (acc).w += (a) * (wr).w + (xv) * (wo).w; \
    } while (0)

__global__ void __launch_bounds__(256, 3) output_kernel(
    const float* __restrict__ x,
    const float* __restrict__ W_rel,   // [64,64] row-major W[o][k]
    const float* __restrict__ b_rel,   // [64]
    const float* __restrict__ W_root,  // [64,64]
    float* __restrict__ out)
{
    __shared__ float Wr[DD * DD];      // Wr[k*64 + o]
    __shared__ float Wo[DD * DD];
    __shared__ float sa[64 * ROWPAD];  // 64 agg rows, padded
    __shared__ float sx[64 * ROWPAD];  // 64 x rows, padded

    int tid = threadIdx.x;
    int nb = blockIdx.x * 64;

    // Transpose-load both weight matrices into shared.
    #pragma unroll
    for (int i = tid; i < DD * DD; i += 256) {
        int o = i >> 6;
        int k = i & 63;
        Wr[k * DD + o] = W_rel[i];
        Wo[k * DD + o] = W_root[i];
    }

    // Stage 64 agg rows + 64 x rows (guard OOB rows in the tail block).
    #pragma unroll
    for (int it = 0; it < 4; it++) {
        int i = tid + it * 256;        // 0..1023 float4 slots
        int row = i >> 4;
        int q = i & 15;
        float4 a4 = make_float4(0.f, 0.f, 0.f, 0.f);
        float4 r4 = make_float4(0.f, 0.f, 0.f, 0.f);
        if (nb + row < NN) {
            a4 = g_agg4[(size_t)(nb + row) * 16 + q];
            r4 = reinterpret_cast<const float4*>(x)[(size_t)(nb + row) * 16 + q];
        }
        reinterpret_cast<float4*>(sa + row * ROWPAD)[q] = a4;
        reinterpret_cast<float4*>(sx + row * ROWPAD)[q] = r4;
    }
    __syncthreads();

    int t = tid >> 4;                  // row-group 0..15 (rows t*4..t*4+3)
    int j = tid & 15;                  // float4 output index

    float4 bias = reinterpret_cast<const float4*>(b_rel)[j];
    float4 acc0 = bias, acc1 = bias, acc2 = bias, acc3 = bias;

    const float* a0 = sa + (t * 4 + 0) * ROWPAD;
    const float* a1 = sa + (t * 4 + 1) * ROWPAD;
    const float* a2 = sa + (t * 4 + 2) * ROWPAD;
    const float* a3 = sa + (t * 4 + 3) * ROWPAD;
    const float* x0 = sx + (t * 4 + 0) * ROWPAD;
    const float* x1 = sx + (t * 4 + 1) * ROWPAD;
    const float* x2 = sx + (t * 4 + 2) * ROWPAD;
    const float* x3 = sx + (t * 4 + 3) * ROWPAD;

    #pragma unroll 2
    for (int kc = 0; kc < DD; kc += 4) {
        // Row segments: 8 LDS.128, broadcast within each 16-lane t-group.
        float4 A0 = *reinterpret_cast<const float4*>(a0 + kc);
        float4 A1 = *reinterpret_cast<const float4*>(a1 + kc);
        float4 A2 = *reinterpret_cast<const float4*>(a2 + kc);
        float4 A3 = *reinterpret_cast<const float4*>(a3 + kc);
        float4 X0 = *reinterpret_cast<const float4*>(x0 + kc);
        float4 X1 = *reinterpret_cast<const float4*>(x1 + kc);
        float4 X2 = *reinterpret_cast<const float4*>(x2 + kc);
        float4 X3 = *reinterpret_cast<const float4*>(x3 + kc);

        // kk = 0
        {
            float4 wr = reinterpret_cast<const float4*>(Wr + (kc + 0) * DD)[j];
            float4 wo = reinterpret_cast<const float4*>(Wo + (kc + 0) * DD)[j];
            FMA4(acc0, A0.x, wr, X0.x, wo);
            FMA4(acc1, A1.x, wr, X1.x, wo);
            FMA4(acc2, A2.x, wr, X2.x, wo);
            FMA4(acc3, A3.x, wr, X3.x, wo);
        }
        // kk = 1
        {
            float4 wr = reinterpret_cast<const float4*>(Wr + (kc + 1) * DD)[j];
            float4 wo = reinterpret_cast<const float4*>(Wo + (kc + 1) * DD)[j];
            FMA4(acc0, A0.y, wr, X0.y, wo);
            FMA4(acc1, A1.y, wr, X1.y, wo);
            FMA4(acc2, A2.y, wr, X2.y, wo);
            FMA4(acc3, A3.y, wr, X3.y, wo);
        }
        // kk = 2
        {
            float4 wr = reinterpret_cast<const float4*>(Wr + (kc + 2) * DD)[j];
            float4 wo = reinterpret_cast<const float4*>(Wo + (kc + 2) * DD)[j];
            FMA4(acc0, A0.z, wr, X0.z, wo);
            FMA4(acc1, A1.z, wr, X1.z, wo);
            FMA4(acc2, A2.z, wr, X2.z, wo);
            FMA4(acc3, A3.z, wr, X3.z, wo);
        }
        // kk = 3
        {
            float4 wr = reinterpret_cast<const float4*>(Wr + (kc + 3) * DD)[j];
            float4 wo = reinterpret_cast<const float4*>(Wo + (kc + 3) * DD)[j];
            FMA4(acc0, A0.w, wr, X0.w, wo);
            FMA4(acc1, A1.w, wr, X1.w, wo);
            FMA4(acc2, A2.w, wr, X2.w, wo);
            FMA4(acc3, A3.w, wr, X3.w, wo);
        }
    }

    float4 accs[4] = {acc0, acc1, acc2, acc3};
    #pragma unroll
    for (int r = 0; r < 4; r++) {
        int nr = nb + t * 4 + r;
        if (nr < NN) {
            float4 v = accs[r];
            v.x = fmaxf(v.x, 0.f);
            v.y = fmaxf(v.y, 0.f);
            v.z = fmaxf(v.z, 0.f);
            v.w = fmaxf(v.w, 0.f);
            reinterpret_cast<float4*>(out)[(size_t)nr * 16 + j] = v;
        }
    }
}

// ---------------------------------------------------------------------------
// Launch: detect -> zero -> scatter -> output (capture stream, no syncs)
// Input order: x, edge_index, edge_attr, W_rel, b_rel, W_root
// ---------------------------------------------------------------------------
extern "C" void kernel_launch(void* const* d_in, const int* in_sizes, int n_in,
                              void* d_out, int out_size)
{
    const float* x     = (const float*)d_in[0];
    const void*  ei    = d_in[1];
    const float* ea    = (const float*)d_in[2];
    const float* Wrel  = (const float*)d_in[3];
    const float* brel  = (const float*)d_in[4];
    const float* Wroot = (const float*)d_in[5];
    float*       out   = (float*)d_out;

    detect_kernel<<<1, 1>>>((const unsigned int*)ei);

    zero_agg_kernel<<<(NN * (DD / 4) + 255) / 256, 256>>>();

    {
        long long total = (long long)EE * 16;
        int blocks = (int)((total + 255) / 256);
        scatter_kernel<<<blocks, 256>>>(x, ei, ea);
    }

    output_kernel<<<(NN + 63) / 64, 256>>>(x, Wrel, brel, Wroot, out);
}

// round 7
// speedup vs baseline: 1.0962x; 1.0962x over previous
#include <cuda_runtime.h>
#include <cstdint>

// Problem constants (match reference setup_inputs)
#define NN 100000
#define EE 1600000
#define DD 64

// Scratch aggregation buffer. float4 for guaranteed 16B alignment.
__device__ float4 g_agg4[(size_t)NN * (DD / 4)];

// 1 if edge_index buffer is int64, 0 if int32 (JAX x64-disabled downgrades).
__device__ int g_idx_is64;

// ---------------------------------------------------------------------------
// Phase 0: detect index width. Indices < 2^17, so int64 => odd words all 0.
// ---------------------------------------------------------------------------
__global__ void detect_kernel(const unsigned int* __restrict__ ei_words) {
    int zeros = 0;
    #pragma unroll
    for (int i = 0; i < 64; i++) zeros += (ei_words[2 * i + 1] == 0u) ? 1 : 0;
    g_idx_is64 = (zeros >= 60) ? 1 : 0;
}

// ---------------------------------------------------------------------------
// Phase B: zero the aggregation buffer
// ---------------------------------------------------------------------------
__global__ void __launch_bounds__(256) zero_agg_kernel() {
    int i = blockIdx.x * blockDim.x + threadIdx.x;
    const int total4 = NN * (DD / 4);
    if (i < total4) g_agg4[i] = make_float4(0.f, 0.f, 0.f, 0.f);
}

// ---------------------------------------------------------------------------
// Phase A: edge scatter. 16 threads/edge, red.global.add.v4 into g_agg.
// ---------------------------------------------------------------------------
__global__ void __launch_bounds__(256) scatter_kernel(
    const float* __restrict__ x,
    const void* __restrict__ edge_index, // [2, E], int32 or int64
    const float* __restrict__ edge_attr)
{
    int gid = blockIdx.x * blockDim.x + threadIdx.x;
    int e = gid >> 4;
    int q = gid & 15;
    if (e >= EE) return;

    int src, dst;
    if (g_idx_is64) {
        const long long* ei = (const long long*)edge_index;
        src = (int)ei[e];
        dst = (int)ei[EE + e];
    } else {
        const int* ei = (const int*)edge_index;
        src = ei[e];
        dst = ei[EE + e];
    }
    float w = edge_attr[e];

    float4 v = reinterpret_cast<const float4*>(x)[(size_t)src * 16 + q];
    v.x *= w; v.y *= w; v.z *= w; v.w *= w;

    float* p = (float*)(g_agg4 + (size_t)dst * 16 + q);
    asm volatile("red.global.add.v4.f32 [%0], {%1, %2, %3, %4};"
                 :: "l"(p), "f"(v.x), "f"(v.y), "f"(v.z), "f"(v.w)
                 : "memory");
}

// ---------------------------------------------------------------------------
// Packed f32x2 helpers (sm_103a). ptxas never auto-fuses FFMA2 from C++.
// ---------------------------------------------------------------------------
__device__ __forceinline__ unsigned long long pack2(float lo, float hi) {
    unsigned long long r;
    asm("mov.b64 %0, {%1, %2};" : "=l"(r)
        : "r"(__float_as_uint(lo)), "r"(__float_as_uint(hi)));
    return r;
}
__device__ __forceinline__ void unpack2(unsigned long long v, float& lo, float& hi) {
    unsigned int a, b;
    asm("mov.b64 {%0, %1}, %2;" : "=r"(a), "=r"(b) : "l"(v));
    lo = __uint_as_float(a);
    hi = __uint_as_float(b);
}
__device__ __forceinline__ void ffma2(unsigned long long& acc,
                                      unsigned long long a,
                                      unsigned long long b) {
    asm("fma.rn.f32x2 %0, %1, %2, %0;" : "+l"(acc) : "l"(a), "l"(b));
}

// ---------------------------------------------------------------------------
// Phase C: out = relu(agg @ W_rel^T + b_rel + x @ W_root^T)
// 256 threads/block, 128 nodes/block. Each thread: 8 rows x 4 outputs,
// accumulated as 16 f32x2 row-pair accumulators via fma.rn.f32x2.
// Per kk: 2 weight LDS.128 (+4 row LDS.128 amortized over 4 kk),
// 16 pack-MOVs, 32 FFMA2 -> 54 issue slots per 128 FMA.
// ---------------------------------------------------------------------------
#define ROWPAD 68
#define RPB 128   // rows (nodes) per block

__global__ void __launch_bounds__(256, 2) output_kernel(
    const float* __restrict__ x,
    const float* __restrict__ W_rel,   // [64,64] row-major W[o][k]
    const float* __restrict__ b_rel,   // [64]
    const float* __restrict__ W_root,  // [64,64]
    float* __restrict__ out)
{
    __shared__ float Wr[DD * DD];       // Wr[k*64 + o]
    __shared__ float Wo[DD * DD];
    __shared__ float sa[RPB * ROWPAD];  // agg rows, padded
    __shared__ float sx[RPB * ROWPAD];  // x rows, padded

    int tid = threadIdx.x;
    int nb = blockIdx.x * RPB;

    // Transpose-load both weight matrices into shared.
    #pragma unroll
    for (int i = tid; i < DD * DD; i += 256) {
        int o = i >> 6;
        int k = i & 63;
        Wr[k * DD + o] = W_rel[i];
        Wo[k * DD + o] = W_root[i];
    }

    // Stage RPB agg rows + RPB x rows (zero OOB rows in the tail block).
    #pragma unroll
    for (int it = 0; it < RPB / 16; it++) {
        int i = tid + it * 256;        // 0..2047 float4 slots
        int row = i >> 4;
        int q = i & 15;
        float4 a4 = make_float4(0.f, 0.f, 0.f, 0.f);
        float4 r4 = make_float4(0.f, 0.f, 0.f, 0.f);
        if (nb + row < NN) {
            a4 = g_agg4[(size_t)(nb + row) * 16 + q];
            r4 = reinterpret_cast<const float4*>(x)[(size_t)(nb + row) * 16 + q];
        }
        reinterpret_cast<float4*>(sa + row * ROWPAD)[q] = a4;
        reinterpret_cast<float4*>(sx + row * ROWPAD)[q] = r4;
    }
    __syncthreads();

    int t = tid >> 4;                  // row group 0..15 -> rows t*8..t*8+7
    int j = tid & 15;                  // output float4 index
    int rb = t * 8;

    // 16 f32x2 accumulators: acc[p][o] holds (row 2p, row 2p+1) for output j*4+o
    float4 bias = reinterpret_cast<const float4*>(b_rel)[j];
    unsigned long long acc[4][4];
    {
        unsigned long long b0 = pack2(bias.x, bias.x);
        unsigned long long b1 = pack2(bias.y, bias.y);
        unsigned long long b2 = pack2(bias.z, bias.z);
        unsigned long long b3 = pack2(bias.w, bias.w);
        #pragma unroll
        for (int p = 0; p < 4; p++) {
            acc[p][0] = b0; acc[p][1] = b1; acc[p][2] = b2; acc[p][3] = b3;
        }
    }

    const float* abase = sa + rb * ROWPAD;
    const float* xbase = sx + rb * ROWPAD;

    #pragma unroll 1
    for (int kc = 0; kc < DD; kc += 4) {
        // 16 row LDS.128 (broadcast within each 16-lane t-group)
        float4 A[8], X[8];
        #pragma unroll
        for (int r = 0; r < 8; r++) {
            A[r] = *reinterpret_cast<const float4*>(abase + r * ROWPAD + kc);
            X[r] = *reinterpret_cast<const float4*>(xbase + r * ROWPAD + kc);
        }

        #define KSTEP(kk, COMP)                                               \
        {                                                                     \
            float4 wr = reinterpret_cast<const float4*>(Wr + (kc + kk) * DD)[j]; \
            float4 wo = reinterpret_cast<const float4*>(Wo + (kc + kk) * DD)[j]; \
            unsigned long long wrp[4] = {                                     \
                pack2(wr.x, wr.x), pack2(wr.y, wr.y),                         \
                pack2(wr.z, wr.z), pack2(wr.w, wr.w)};                        \
            unsigned long long wop[4] = {                                     \
                pack2(wo.x, wo.x), pack2(wo.y, wo.y),                         \
                pack2(wo.z, wo.z), pack2(wo.w, wo.w)};                        \
            _Pragma("unroll")                                                 \
            for (int p = 0; p < 4; p++) {                                     \
                unsigned long long ap = pack2(A[2*p].COMP, A[2*p+1].COMP);    \
                unsigned long long xp = pack2(X[2*p].COMP, X[2*p+1].COMP);    \
                ffma2(acc[p][0], ap, wrp[0]);                                 \
                ffma2(acc[p][0], xp, wop[0]);                                 \
                ffma2(acc[p][1], ap, wrp[1]);                                 \
                ffma2(acc[p][1], xp, wop[1]);                                 \
                ffma2(acc[p][2], ap, wrp[2]);                                 \
                ffma2(acc[p][2], xp, wop[2]);                                 \
                ffma2(acc[p][3], ap, wrp[3]);                                 \
                ffma2(acc[p][3], xp, wop[3]);                                 \
            }                                                                 \
        }
        KSTEP(0, x)
        KSTEP(1, y)
        KSTEP(2, z)
        KSTEP(3, w)
        #undef KSTEP
    }

    // Epilogue: unpack row pairs, relu, store float4 per row.
    #pragma unroll
    for (int p = 0; p < 4; p++) {
        float4 v0, v1;
        unpack2(acc[p][0], v0.x, v1.x);
        unpack2(acc[p][1], v0.y, v1.y);
        unpack2(acc[p][2], v0.z, v1.z);
        unpack2(acc[p][3], v0.w, v1.w);
        int r0 = nb + rb + 2 * p;
        int r1 = r0 + 1;
        if (r0 < NN) {
            v0.x = fmaxf(v0.x, 0.f); v0.y = fmaxf(v0.y, 0.f);
            v0.z = fmaxf(v0.z, 0.f); v0.w = fmaxf(v0.w, 0.f);
            reinterpret_cast<float4*>(out)[(size_t)r0 * 16 + j] = v0;
        }
        if (r1 < NN) {
            v1.x = fmaxf(v1.x, 0.f); v1.y = fmaxf(v1.y, 0.f);
            v1.z = fmaxf(v1.z, 0.f); v1.w = fmaxf(v1.w, 0.f);
            reinterpret_cast<float4*>(out)[(size_t)r1 * 16 + j] = v1;
        }
    }
}

// ---------------------------------------------------------------------------
// Launch: detect -> zero -> scatter -> output (capture stream, no syncs)
// Input order: x, edge_index, edge_attr, W_rel, b_rel, W_root
// ---------------------------------------------------------------------------
extern "C" void kernel_launch(void* const* d_in, const int* in_sizes, int n_in,
                              void* d_out, int out_size)
{
    const float* x     = (const float*)d_in[0];
    const void*  ei    = d_in[1];
    const float* ea    = (const float*)d_in[2];
    const float* Wrel  = (const float*)d_in[3];
    const float* brel  = (const float*)d_in[4];
    const float* Wroot = (const float*)d_in[5];
    float*       out   = (float*)d_out;

    detect_kernel<<<1, 1>>>((const unsigned int*)ei);

    zero_agg_kernel<<<(NN * (DD / 4) + 255) / 256, 256>>>();

    {
        long long total = (long long)EE * 16;
        int blocks = (int)((total + 255) / 256);
        scatter_kernel<<<blocks, 256>>>(x, ei, ea);
    }

    output_kernel<<<(NN + RPB - 1) / RPB, 256>>>(x, Wrel, brel, Wroot, out);
}